// round 3
// baseline (speedup 1.0000x reference)
#include <cuda_runtime.h>
#include <cuda_bf16.h>
#include <cstdint>
#include <math.h>

// ===================== problem constants =====================
#define N_ROWS   262144
#define G_SZ     1048576
#define TILE_R   256
#define N_TILES  1024      // N_ROWS / 256
#define GRID1    152

// SMEM layout (byte offsets from dynamic smem base)
#define OFF_WFRAG 0          // 4 layers x 8kt x 16nt x 32 lanes x 8B = 131072
#define OFF_STAGE 131072     // 256 rows x 272 B = 69632 (also weight-load tmp 32KB)
#define OFF_BIAS  200704     // 4 x 128 fp32
#define OFF_LN    202752     // ln1g, ln1b, ln2g, ln2b (128 each)
#define OFF_W5S   204800     // float4[128] head weights (cols 0,1,2,10)
#define OFF_B5    206848
#define OFF_SCL   206864
#define SMEM_DYN  206976

#define STAGE_STRIDE_B 272   // 128 bf16 + 8 pad  (17 x 16B, conflict-free ldmatrix)

// ===================== device scratch =====================
__device__ float4 g_scratch[N_ROWS];     // sigmoid xyz0,xyz1,xyz2,opa per row
__device__ float  g_blocksum[GRID1];
__device__ float  g_dc;                  // max(d, 1e-8)
__device__ float  g_diff;                // fl(exp(fl(d-6))) - fl(exp(-6))

// ===================== helpers =====================
__device__ __forceinline__ uint32_t smem_to_u32(const void* smem_ptr) {
    uint32_t addr;
    asm("{ .reg .u64 tmp; cvta.to.shared.u64 tmp, %1; cvt.u32.u64 %0, tmp; }"
        : "=r"(addr) : "l"(smem_ptr));
    return addr;
}

__device__ __forceinline__ void ldmA(uint32_t addr, uint32_t& a0, uint32_t& a1,
                                     uint32_t& a2, uint32_t& a3) {
    asm volatile("ldmatrix.sync.aligned.m8n8.x4.shared.b16 {%0,%1,%2,%3}, [%4];"
                 : "=r"(a0), "=r"(a1), "=r"(a2), "=r"(a3) : "r"(addr));
}

__device__ __forceinline__ void mma16816(float* c,
                                         uint32_t a0, uint32_t a1, uint32_t a2, uint32_t a3,
                                         uint32_t b0, uint32_t b1) {
    asm volatile("mma.sync.aligned.m16n8k16.row.col.f32.bf16.bf16.f32 "
                 "{%0,%1,%2,%3},{%4,%5,%6,%7},{%8,%9},{%0,%1,%2,%3};"
                 : "+f"(c[0]), "+f"(c[1]), "+f"(c[2]), "+f"(c[3])
                 : "r"(a0), "r"(a1), "r"(a2), "r"(a3), "r"(b0), "r"(b1));
}

__device__ __forceinline__ uint32_t packbf(float lo, float hi) {
    uint32_t w;
    asm("cvt.rn.bf16x2.f32 %0, %1, %2;" : "=r"(w) : "f"(hi), "f"(lo));
    return w;
}

__device__ __forceinline__ float safe_sig(float x) {
    x = fminf(fmaxf(x, -9.21f), 9.21f);
    return 1.0f / (1.0f + expf(-x));
}

struct Params {
    const float* inst;
    const float* anchor;
    const float* aemb;
    const float* w[4];
    const float* b[4];
    const float* ln1g; const float* ln1b;
    const float* ln2g; const float* ln2b;
    const float* w5; const float* b5; const float* scale;
};

// ===================== main persistent kernel =====================
__global__ void __launch_bounds__(256, 1) k_main(Params p) {
    extern __shared__ __align__(16) char base[];
    const uint32_t base_u = smem_to_u32(base);

    const int tid = threadIdx.x;
    const int wrp = tid >> 5;
    const int ln  = tid & 31;
    const int tig = ln & 3;        // thread-in-group
    const int grp = ln >> 2;       // group id (row within 8)

    // ---------- init: pre-swizzle weights into fragment layout ----------
    {
        uint32_t* tmp = (uint32_t*)(base + OFF_STAGE);   // 8192 u32 = 32KB
        uint2* wf = (uint2*)(base + OFF_WFRAG);
        for (int l = 0; l < 4; l++) {
            const float4* ws = (const float4*)p.w[l];
            #pragma unroll
            for (int i = 0; i < 16; i++) {
                int idx = i * 256 + tid;              // 4096 float4
                float4 v = ws[idx];
                int k = idx >> 5;
                int nw = (idx & 31) * 2;              // u32 word within row (64 words)
                tmp[k * 64 + nw]     = packbf(v.x, v.y);
                tmp[k * 64 + nw + 1] = packbf(v.z, v.w);
            }
            __syncthreads();
            // build B fragments: b0 = w[k0..k0+1][n], b1 = w[k0+8..k0+9][n]
            for (int ft = wrp; ft < 128; ft += 8) {
                int kt = ft >> 4, nt = ft & 15;
                int k0 = kt * 16 + tig * 2;
                int n  = nt * 8 + grp;
                uint32_t sel = (n & 1) ? 0x7632u : 0x5410u;
                uint32_t t0 = tmp[k0 * 64 + (n >> 1)];
                uint32_t t1 = tmp[(k0 + 1) * 64 + (n >> 1)];
                uint32_t t2 = tmp[(k0 + 8) * 64 + (n >> 1)];
                uint32_t t3 = tmp[(k0 + 9) * 64 + (n >> 1)];
                uint2 bv;
                bv.x = __byte_perm(t0, t1, sel);
                bv.y = __byte_perm(t2, t3, sel);
                wf[(l * 128 + ft) * 32 + ln] = bv;
            }
            __syncthreads();
        }
        // biases, LN params, head
        if (tid < 128) {
            float* bs = (float*)(base + OFF_BIAS);
            bs[tid]       = p.b[0][tid];
            bs[128 + tid] = p.b[1][tid];
            bs[256 + tid] = p.b[2][tid];
            bs[384 + tid] = p.b[3][tid];
            float* lnp = (float*)(base + OFF_LN);
            lnp[tid]       = p.ln1g[tid];
            lnp[128 + tid] = p.ln1b[tid];
            lnp[256 + tid] = p.ln2g[tid];
            lnp[384 + tid] = p.ln2b[tid];
            float4 w5v;
            w5v.x = p.w5[tid * 86 + 0];
            w5v.y = p.w5[tid * 86 + 1];
            w5v.z = p.w5[tid * 86 + 2];
            w5v.w = p.w5[tid * 86 + 10];
            ((float4*)(base + OFF_W5S))[tid] = w5v;
        }
        if (tid == 0) {
            *(float4*)(base + OFF_B5)  = make_float4(p.b5[0], p.b5[1], p.b5[2], p.b5[10]);
            *(float4*)(base + OFF_SCL) = make_float4(p.scale[0], p.scale[1], p.scale[2], p.scale[10]);
        }
    }
    __syncthreads();

    const float4* inst4 = (const float4*)p.inst;
    const float4* aemb4 = (const float4*)p.aemb;
    uint2* st2 = (uint2*)(base + OFF_STAGE);
    const uint2* wf = (const uint2*)(base + OFF_WFRAG);
    const float4 b5v = *(const float4*)(base + OFF_B5);
    const float4 scv = *(const float4*)(base + OFF_SCL);
    const float4* w5s = (const float4*)(base + OFF_W5S);

    // ldmatrix per-lane base address (within a tile): warp rows = wrp*32
    // lane -> row offset (ln&15), col byte ((ln>>4)*16)
    const uint32_t lm_base = base_u + OFF_STAGE
                           + (uint32_t)(wrp * 32 + (ln & 15)) * STAGE_STRIDE_B
                           + (uint32_t)((ln >> 4) << 4);

    float part = 0.0f;
    float acc[2][16][4];
    uint32_t hp[2][16][2];

    for (int tile = blockIdx.x; tile < N_TILES; tile += GRID1) {
        // ---- stage x = inst + aemb as bf16, row-major, 272B stride ----
        {
            int gb = tile * 8192;
            #pragma unroll 4
            for (int i = 0; i < 32; i++) {
                int idx = i * 256 + tid;
                float4 a = inst4[gb + idx];
                float4 b = aemb4[gb + idx];
                uint32_t w0 = packbf(a.x + b.x, a.y + b.y);
                uint32_t w1 = packbf(a.z + b.z, a.w + b.w);
                int row = idx >> 5, q = idx & 31;
                st2[row * 34 + q] = make_uint2(w0, w1);
            }
        }
        __syncthreads();

        // ---- layer 0: A via ldmatrix ----
        #pragma unroll
        for (int mb = 0; mb < 2; mb++)
            #pragma unroll
            for (int nt = 0; nt < 16; nt++)
                #pragma unroll
                for (int j = 0; j < 4; j++) acc[mb][nt][j] = 0.0f;

        {
            const uint2* wfl = wf + ln;   // layer 0
            #pragma unroll
            for (int kt = 0; kt < 8; kt++) {
                uint32_t a00, a01, a02, a03, a10, a11, a12, a13;
                ldmA(lm_base + kt * 32,               a00, a01, a02, a03);
                ldmA(lm_base + 16 * STAGE_STRIDE_B + kt * 32, a10, a11, a12, a13);
                #pragma unroll
                for (int nt = 0; nt < 16; nt++) {
                    uint2 bv = wfl[(kt * 16 + nt) * 32];
                    mma16816(acc[0][nt], a00, a01, a02, a03, bv.x, bv.y);
                    mma16816(acc[1][nt], a10, a11, a12, a13, bv.x, bv.y);
                }
            }
        }

        // bias0 + relu -> pack hp
        {
            const float2* bs2 = (const float2*)((const float*)(base + OFF_BIAS));
            #pragma unroll
            for (int nt = 0; nt < 16; nt++) {
                float2 bb = bs2[nt * 4 + tig];
                #pragma unroll
                for (int mb = 0; mb < 2; mb++) {
                    float v0 = fmaxf(acc[mb][nt][0] + bb.x, 0.0f);
                    float v1 = fmaxf(acc[mb][nt][1] + bb.y, 0.0f);
                    float v2 = fmaxf(acc[mb][nt][2] + bb.x, 0.0f);
                    float v3 = fmaxf(acc[mb][nt][3] + bb.y, 0.0f);
                    hp[mb][nt][0] = packbf(v0, v1);
                    hp[mb][nt][1] = packbf(v2, v3);
                }
            }
        }

        // ---- layers 1..3 (register-chained) ----
        for (int lidx = 1; lidx < 4; lidx++) {
            #pragma unroll
            for (int mb = 0; mb < 2; mb++)
                #pragma unroll
                for (int nt = 0; nt < 16; nt++)
                    #pragma unroll
                    for (int j = 0; j < 4; j++) acc[mb][nt][j] = 0.0f;

            const uint2* wfl = wf + lidx * 4096 + ln;
            #pragma unroll
            for (int kt = 0; kt < 8; kt++) {
                uint32_t a00 = hp[0][2 * kt][0],   a01 = hp[0][2 * kt][1];
                uint32_t a02 = hp[0][2 * kt + 1][0], a03 = hp[0][2 * kt + 1][1];
                uint32_t a10 = hp[1][2 * kt][0],   a11 = hp[1][2 * kt][1];
                uint32_t a12 = hp[1][2 * kt + 1][0], a13 = hp[1][2 * kt + 1][1];
                #pragma unroll
                for (int nt = 0; nt < 16; nt++) {
                    uint2 bv = wfl[(kt * 16 + nt) * 32];
                    mma16816(acc[0][nt], a00, a01, a02, a03, bv.x, bv.y);
                    mma16816(acc[1][nt], a10, a11, a12, a13, bv.x, bv.y);
                }
            }

            // bias + relu
            {
                const float2* bs2 = (const float2*)((const float*)(base + OFF_BIAS) + lidx * 128);
                #pragma unroll
                for (int nt = 0; nt < 16; nt++) {
                    float2 bb = bs2[nt * 4 + tig];
                    #pragma unroll
                    for (int mb = 0; mb < 2; mb++) {
                        acc[mb][nt][0] = fmaxf(acc[mb][nt][0] + bb.x, 0.0f);
                        acc[mb][nt][1] = fmaxf(acc[mb][nt][1] + bb.y, 0.0f);
                        acc[mb][nt][2] = fmaxf(acc[mb][nt][2] + bb.x, 0.0f);
                        acc[mb][nt][3] = fmaxf(acc[mb][nt][3] + bb.y, 0.0f);
                    }
                }
            }

            // layernorm after layers 2 and 4 (lidx 1, 3)
            if (lidx & 1) {
                const float* lnp = (const float*)(base + OFF_LN) + ((lidx == 1) ? 0 : 256);
                const float2* g2 = (const float2*)lnp;
                const float2* b2 = (const float2*)(lnp + 128);
                #pragma unroll
                for (int mb = 0; mb < 2; mb++) {
                    float sA = 0.0f, sB = 0.0f;
                    #pragma unroll
                    for (int nt = 0; nt < 16; nt++) {
                        sA += acc[mb][nt][0] + acc[mb][nt][1];
                        sB += acc[mb][nt][2] + acc[mb][nt][3];
                    }
                    sA += __shfl_xor_sync(0xffffffffu, sA, 1);
                    sA += __shfl_xor_sync(0xffffffffu, sA, 2);
                    sB += __shfl_xor_sync(0xffffffffu, sB, 1);
                    sB += __shfl_xor_sync(0xffffffffu, sB, 2);
                    float muA = sA * (1.0f / 128.0f);
                    float muB = sB * (1.0f / 128.0f);
                    float vA = 0.0f, vB = 0.0f;
                    #pragma unroll
                    for (int nt = 0; nt < 16; nt++) {
                        float t0 = acc[mb][nt][0] - muA, t1 = acc[mb][nt][1] - muA;
                        float t2 = acc[mb][nt][2] - muB, t3 = acc[mb][nt][3] - muB;
                        vA += t0 * t0 + t1 * t1;
                        vB += t2 * t2 + t3 * t3;
                    }
                    vA += __shfl_xor_sync(0xffffffffu, vA, 1);
                    vA += __shfl_xor_sync(0xffffffffu, vA, 2);
                    vB += __shfl_xor_sync(0xffffffffu, vB, 1);
                    vB += __shfl_xor_sync(0xffffffffu, vB, 2);
                    float rA = rsqrtf(vA * (1.0f / 128.0f) + 1e-5f);
                    float rB = rsqrtf(vB * (1.0f / 128.0f) + 1e-5f);
                    #pragma unroll
                    for (int nt = 0; nt < 16; nt++) {
                        float2 gg = g2[nt * 4 + tig];
                        float2 bb = b2[nt * 4 + tig];
                        acc[mb][nt][0] = (acc[mb][nt][0] - muA) * rA * gg.x + bb.x;
                        acc[mb][nt][1] = (acc[mb][nt][1] - muA) * rA * gg.y + bb.y;
                        acc[mb][nt][2] = (acc[mb][nt][2] - muB) * rB * gg.x + bb.x;
                        acc[mb][nt][3] = (acc[mb][nt][3] - muB) * rB * gg.y + bb.y;
                    }
                }
            }

            if (lidx < 3) {
                #pragma unroll
                for (int nt = 0; nt < 16; nt++)
                    #pragma unroll
                    for (int mb = 0; mb < 2; mb++) {
                        hp[mb][nt][0] = packbf(acc[mb][nt][0], acc[mb][nt][1]);
                        hp[mb][nt][1] = packbf(acc[mb][nt][2], acc[mb][nt][3]);
                    }
            }
        }

        // ---- head: 4-column dot + anchor + sigmoid ----
        #pragma unroll
        for (int mb = 0; mb < 2; mb++) {
            float dA0 = 0.f, dA1 = 0.f, dA2 = 0.f, dA3 = 0.f;
            float dB0 = 0.f, dB1 = 0.f, dB2 = 0.f, dB3 = 0.f;
            #pragma unroll
            for (int nt = 0; nt < 16; nt++) {
                int c = nt * 8 + tig * 2;
                float4 wv0 = w5s[c];
                float4 wv1 = w5s[c + 1];
                float hA0 = acc[mb][nt][0], hA1 = acc[mb][nt][1];
                float hB0 = acc[mb][nt][2], hB1 = acc[mb][nt][3];
                dA0 = fmaf(hA0, wv0.x, fmaf(hA1, wv1.x, dA0));
                dA1 = fmaf(hA0, wv0.y, fmaf(hA1, wv1.y, dA1));
                dA2 = fmaf(hA0, wv0.z, fmaf(hA1, wv1.z, dA2));
                dA3 = fmaf(hA0, wv0.w, fmaf(hA1, wv1.w, dA3));
                dB0 = fmaf(hB0, wv0.x, fmaf(hB1, wv1.x, dB0));
                dB1 = fmaf(hB0, wv0.y, fmaf(hB1, wv1.y, dB1));
                dB2 = fmaf(hB0, wv0.z, fmaf(hB1, wv1.z, dB2));
                dB3 = fmaf(hB0, wv0.w, fmaf(hB1, wv1.w, dB3));
            }
            #pragma unroll
            for (int off = 1; off <= 2; off <<= 1) {
                dA0 += __shfl_xor_sync(0xffffffffu, dA0, off);
                dA1 += __shfl_xor_sync(0xffffffffu, dA1, off);
                dA2 += __shfl_xor_sync(0xffffffffu, dA2, off);
                dA3 += __shfl_xor_sync(0xffffffffu, dA3, off);
                dB0 += __shfl_xor_sync(0xffffffffu, dB0, off);
                dB1 += __shfl_xor_sync(0xffffffffu, dB1, off);
                dB2 += __shfl_xor_sync(0xffffffffu, dB2, off);
                dB3 += __shfl_xor_sync(0xffffffffu, dB3, off);
            }
            if (tig == 0) {
                int rA = tile * TILE_R + wrp * 32 + mb * 16 + grp;
                #pragma unroll
                for (int half = 0; half < 2; half++) {
                    int row = rA + half * 8;
                    float e0 = half ? dB0 : dA0;
                    float e1 = half ? dB1 : dA1;
                    float e2 = half ? dB2 : dA2;
                    float e3 = half ? dB3 : dA3;
                    const float* ar = p.anchor + (size_t)row * 86;
                    float o0  = (e0 + b5v.x) * scv.x + ar[0];
                    float o1  = (e1 + b5v.y) * scv.y + ar[1];
                    float o2  = (e2 + b5v.z) * scv.z + ar[2];
                    float o10 = (e3 + b5v.w) * scv.w + ar[10];
                    float x0 = safe_sig(o0), x1 = safe_sig(o1), x2 = safe_sig(o2);
                    float op = safe_sig(o10);
                    g_scratch[row] = make_float4(x0, x1, x2, op);
                    part += 1.0f / fabsf(x0) + 1.0f / fabsf(x1) + 1.0f / fabsf(x2);
                }
            }
        }
        __syncthreads();   // protect stage reuse next tile
    }

    // ---- block reduction of partial sums (reuse stage smem) ----
    float* red = (float*)(base + OFF_STAGE);
    red[tid] = part;
    __syncthreads();
    #pragma unroll
    for (int st = 128; st > 0; st >>= 1) {
        if (tid < st) red[tid] += red[tid + st];
        __syncthreads();
    }
    if (tid == 0) g_blocksum[blockIdx.x] = red[0];
}

// ===================== reduce: scalar d, divisor, exp diff =====================
__global__ void k_reduce() {
    __shared__ float s[256];
    int tid = threadIdx.x;
    s[tid] = (tid < GRID1) ? g_blocksum[tid] : 0.0f;
    __syncthreads();
    #pragma unroll
    for (int st = 128; st > 0; st >>= 1) {
        if (tid < st) s[tid] += s[tid + st];
        __syncthreads();
    }
    if (tid == 0) {
        float total = s[0];
        float d = 1.0f / total;
        g_dc = fmaxf(d, 1e-8f);
        float arg = d - 6.0f;                       // fp32 rounding, like reference
        float e1 = (float)exp((double)arg);         // correctly-rounded fp32 exp
        float e2 = (float)exp(-6.0);
        g_diff = e1 - e2;
    }
}

// ===================== scatter-add into output =====================
__global__ void k_scatter(const int* __restrict__ idxs, float* __restrict__ out) {
    int i = blockIdx.x * blockDim.x + threadIdx.x;
    if (i >= N_ROWS) return;
    int idx = idxs[i];
    float4 s = g_scratch[i];
    float dc = g_dc, df = g_diff;
    out[(size_t)idx * 3 + 0] += (s.x / dc) * df;
    out[(size_t)idx * 3 + 1] += (s.y / dc) * df;
    out[(size_t)idx * 3 + 2] += (s.z / dc) * df;
    out[(size_t)3 * G_SZ + idx] += 0.05f * s.w;
}

// ===================== launch =====================
extern "C" void kernel_launch(void* const* d_in, const int* in_sizes, int n_in,
                              void* d_out, int out_size) {
    Params p;
    p.inst   = (const float*)d_in[0];
    p.anchor = (const float*)d_in[1];
    p.aemb   = (const float*)d_in[2];
    const float* means = (const float*)d_in[3];
    const float* opac  = (const float*)d_in[4];
    p.w[0] = (const float*)d_in[5];  p.b[0] = (const float*)d_in[6];
    p.w[1] = (const float*)d_in[7];  p.b[1] = (const float*)d_in[8];
    p.ln1g = (const float*)d_in[9];  p.ln1b = (const float*)d_in[10];
    p.w[2] = (const float*)d_in[11]; p.b[2] = (const float*)d_in[12];
    p.w[3] = (const float*)d_in[13]; p.b[3] = (const float*)d_in[14];
    p.ln2g = (const float*)d_in[15]; p.ln2b = (const float*)d_in[16];
    p.w5 = (const float*)d_in[17]; p.b5 = (const float*)d_in[18];
    p.scale = (const float*)d_in[19];
    const int* anchor_idxs = (const int*)d_in[20];
    float* out = (float*)d_out;

    cudaFuncSetAttribute(k_main, cudaFuncAttributeMaxDynamicSharedMemorySize, SMEM_DYN);

    // output copies (overwrite the poison) — independent of MLP
    cudaMemcpyAsync(out, means, (size_t)3 * G_SZ * sizeof(float),
                    cudaMemcpyDeviceToDevice, 0);
    cudaMemcpyAsync(out + (size_t)3 * G_SZ, opac, (size_t)G_SZ * sizeof(float),
                    cudaMemcpyDeviceToDevice, 0);

    k_main<<<GRID1, 256, SMEM_DYN>>>(p);
    k_reduce<<<1, 256>>>();
    k_scatter<<<N_ROWS / 256, 256>>>(anchor_idxs, out);
}